// round 9
// baseline (speedup 1.0000x reference)
#include <cuda_runtime.h>
#include <cstdint>

// Wilson-Cowan, N=2^20, 100 serial steps.
// R9: warp-specialized pipe split. Temporal dithering (R7/R8) only reached 80%
//     of the dual-pipe floor because one instruction stream alternates
//     FMA-heavy / MUFU-heavy phases. Now warps specialize:
//       gwid % 5 == 4  -> exp warp: MUFU-free sigmoid (FMA/ALU), all steps
//       otherwise      -> tanh warp: tanh.approx.f32 (MUFU), all steps
//     Per-SMSP balance at 4:1 -> FMA 252 cyc vs MUFU 256 cyc per 5 warp-steps.
//     The per-cycle warp arbiter co-saturates both pipes statistically.

typedef unsigned long long u64;

__device__ __forceinline__ u64 pack2(float lo, float hi) {
    u64 r; asm("mov.b64 %0, {%1, %2};" : "=l"(r) : "f"(lo), "f"(hi)); return r;
}
__device__ __forceinline__ void unpack2(float& lo, float& hi, u64 v) {
    asm("mov.b64 {%0, %1}, %2;" : "=f"(lo), "=f"(hi) : "l"(v));
}
__device__ __forceinline__ u64 fma2(u64 a, u64 b, u64 c) {
    u64 d; asm("fma.rn.f32x2 %0, %1, %2, %3;" : "=l"(d) : "l"(a), "l"(b), "l"(c)); return d;
}
__device__ __forceinline__ u64 add2(u64 a, u64 b) {
    u64 d; asm("add.rn.f32x2 %0, %1, %2;" : "=l"(d) : "l"(a), "l"(b)); return d;
}
__device__ __forceinline__ u64 mul2(u64 a, u64 b) {
    u64 d; asm("mul.rn.f32x2 %0, %1, %2;" : "=l"(d) : "l"(a), "l"(b)); return d;
}
__device__ __forceinline__ float tanhf_a(float x) {
    float r; asm("tanh.approx.f32 %0, %1;" : "=f"(r) : "f"(x)); return r;
}

#define LOG2E 1.4426950408889634f
#define SIGN2 0x8000000080000000ULL

__global__ __launch_bounds__(128, 8)
void wilson_cowan_kernel(const float4* __restrict__ E0,
                         const float4* __restrict__ I0,
                         const float4* __restrict__ IextE,
                         const float4* __restrict__ IextI,
                         const int*    __restrict__ steps_ptr,
                         float* __restrict__ out,
                         int n, int n4, int out_size)
{
    int i = blockIdx.x * blockDim.x + threadIdx.x;

    if (blockIdx.x == 0 && threadIdx.x == 0) {
        for (int k = 2 * n; k < out_size; ++k) out[k] = 0.0f;
    }
    if (i >= n4) return;

    const int steps = steps_ptr ? __ldg(steps_ptr) : 100;

    float4 e4  = E0[i];
    float4 i4  = I0[i];
    float4 xe4 = IextE[i];
    float4 xi4 = IextI[i];

    u64 E2[2] = { pack2(e4.x, e4.y), pack2(e4.z, e4.w) };
    u64 I2[2] = { pack2(i4.x, i4.y), pack2(i4.z, i4.w) };

    const u64 ME  = pack2(0.99f, 0.99f);
    const u64 MI  = pack2(0.98f, 0.98f);

    int gwid = i >> 5;                  // global warp id (uniform per warp)

    if (gwid % 5 != 4) {
        // ================== tanh warp (MUFU path) ==================
        // y = 0.5*(input-4); E' = 0.99E + 0.005(1+tanh(yE));
        //                    I' = 0.98I + 0.01 (1+tanh(yI))
        u64 cE2[2] = { pack2(0.5f*(xe4.x-4.0f), 0.5f*(xe4.y-4.0f)),
                       pack2(0.5f*(xe4.z-4.0f), 0.5f*(xe4.w-4.0f)) };
        u64 cI2[2] = { pack2(0.5f*(xi4.x-4.0f), 0.5f*(xi4.y-4.0f)),
                       pack2(0.5f*(xi4.z-4.0f), 0.5f*(xi4.w-4.0f)) };
        const u64 AEE = pack2( 6.0f,  6.0f);
        const u64 AEI = pack2(-2.0f, -2.0f);
        const u64 AIE = pack2( 6.5f,  6.5f);
        const u64 AII = pack2(-5.5f, -5.5f);
        const u64 BE  = pack2(0.005f, 0.005f);
        const u64 BI  = pack2(0.01f,  0.01f);

        for (int s = 0; s < steps; ++s) {
            #pragma unroll
            for (int p = 0; p < 2; ++p) {
                u64 yE = fma2(AEE, E2[p], fma2(AEI, I2[p], cE2[p]));
                u64 yI = fma2(AIE, E2[p], fma2(AII, I2[p], cI2[p]));
                float a, b, c, d;
                unpack2(a, b, yE);
                unpack2(c, d, yI);
                u64 tE = pack2(tanhf_a(a), tanhf_a(b));
                u64 tI = pack2(tanhf_a(c), tanhf_a(d));
                E2[p] = fma2(BE, tE, fma2(ME, E2[p], BE));
                I2[p] = fma2(BI, tI, fma2(MI, I2[p], BI));
            }
        }
    } else {
        // ================== exp warp (FMA/ALU path, MUFU-free) ==================
        // s = L*(4-input); sigma = 1/(1+2^s); shared Newton-2 reciprocal.
        u64 sE0 = pack2(LOG2E*(4.0f-xe4.x), LOG2E*(4.0f-xe4.y));
        u64 sE1 = pack2(LOG2E*(4.0f-xe4.z), LOG2E*(4.0f-xe4.w));
        u64 sI0 = pack2(LOG2E*(4.0f-xi4.x), LOG2E*(4.0f-xi4.y));
        u64 sI1 = pack2(LOG2E*(4.0f-xi4.z), LOG2E*(4.0f-xi4.w));
        u64 sEc[2] = { sE0, sE1 };
        u64 sIc[2] = { sI0, sI1 };
        const u64 XEE = pack2(-12.0f*LOG2E, -12.0f*LOG2E);
        const u64 XEI = pack2(  4.0f*LOG2E,   4.0f*LOG2E);
        const u64 XIE = pack2(-13.0f*LOG2E, -13.0f*LOG2E);
        const u64 XII = pack2( 11.0f*LOG2E,  11.0f*LOG2E);
        const u64 KE  = pack2(0.01f, 0.01f);
        const u64 KI  = pack2(0.02f, 0.02f);
        const u64 MAG  = pack2(12582912.0f, 12582912.0f);   // 1.5*2^23
        const u64 NEG1 = pack2(-1.0f, -1.0f);
        const u64 ONE  = pack2( 1.0f,  1.0f);
        const u64 TWO  = pack2( 2.0f,  2.0f);
        const u64 A1 = pack2(0.69314718f, 0.69314718f);
        const u64 A2 = pack2(0.24022651f, 0.24022651f);
        const u64 A3 = pack2(0.05550411f, 0.05550411f);
        const u64 A4 = pack2(0.00961813f, 0.00961813f);

        auto exp2_2 = [&](u64 s2) -> u64 {
            u64 m2 = add2(s2, MAG);        // low bits hold rint(s)
            u64 d2 = fma2(MAG, NEG1, m2);  // float(rint(s)), exact
            u64 f2 = fma2(d2, NEG1, s2);   // f in [-0.5, 0.5]
            u64 p  = fma2(A4, f2, A3);
            p = fma2(p, f2, A2);
            p = fma2(p, f2, A1);
            p = fma2(p, f2, ONE);
            float mlo, mhi, plo, phi;
            unpack2(mlo, mhi, m2);
            unpack2(plo, phi, p);
            int zlo = __float_as_int(plo) + (__float_as_int(mlo) << 23);
            int zhi = __float_as_int(phi) + (__float_as_int(mhi) << 23);
            return pack2(__int_as_float(zlo), __int_as_float(zhi));
        };

        for (int s = 0; s < steps; ++s) {
            #pragma unroll
            for (int p = 0; p < 2; ++p) {
                u64 sE = fma2(XEE, E2[p], fma2(XEI, I2[p], sEc[p]));
                u64 sI = fma2(XIE, E2[p], fma2(XII, I2[p], sIc[p]));
                u64 zE = exp2_2(sE);           // s_E in [-11.6, 11.6]
                u64 zI = exp2_2(sI);           // s_I in [-13.0, 21.7]
                u64 wE = add2(zE, ONE);
                u64 wI = add2(zI, ONE);
                u64 P  = mul2(wE, wI);         // <= ~1e10, normal
                float plo, phi;
                unpack2(plo, phi, P);
                u64 r = pack2(__int_as_float(0x7EF311C3 - __float_as_int(plo)),
                              __int_as_float(0x7EF311C3 - __float_as_int(phi)));
                r = mul2(r, fma2(P, r ^ SIGN2, TWO));   // Newton 1
                r = mul2(r, fma2(P, r ^ SIGN2, TWO));   // Newton 2: ~1e-6
                u64 gE = mul2(r, wI);          // sigma_E = 1/wE
                u64 gI = mul2(r, wE);          // sigma_I = 1/wI
                E2[p] = fma2(KE, gE, mul2(ME, E2[p]));
                I2[p] = fma2(KI, gI, mul2(MI, I2[p]));
            }
        }
    }

    float4 eo, io;
    unpack2(eo.x, eo.y, E2[0]); unpack2(eo.z, eo.w, E2[1]);
    unpack2(io.x, io.y, I2[0]); unpack2(io.z, io.w, I2[1]);
    eo.x = __saturatef(eo.x); eo.y = __saturatef(eo.y);
    eo.z = __saturatef(eo.z); eo.w = __saturatef(eo.w);
    io.x = __saturatef(io.x); io.y = __saturatef(io.y);
    io.z = __saturatef(io.z); io.w = __saturatef(io.w);

    reinterpret_cast<float4*>(out)[i]     = eo;
    reinterpret_cast<float4*>(out + n)[i] = io;
}

extern "C" void kernel_launch(void* const* d_in, const int* in_sizes, int n_in,
                              void* d_out, int out_size)
{
    const float4* E0    = (const float4*)d_in[0];
    const float4* I0    = (const float4*)d_in[1];
    const float4* IextE = (const float4*)d_in[2];
    const float4* IextI = (const float4*)d_in[3];
    const int* steps_ptr = (n_in >= 5) ? (const int*)d_in[4] : nullptr;

    int n = in_sizes[0];
    int n4 = n / 4;                     // 4 elems per thread = 1 float4
    int threads = 128;
    int blocks = (n4 + threads - 1) / threads;   // 2048

    wilson_cowan_kernel<<<blocks, threads>>>(E0, I0, IextE, IextI, steps_ptr,
                                             (float*)d_out, n, n4, out_size);
}

// round 10
// speedup vs baseline: 1.3325x; 1.3325x over previous
#include <cuda_runtime.h>
#include <cstdint>

// Wilson-Cowan, N=2^20, 100 serial steps.
// R10: R8 skeleton (best: 49.5us) + burst-breaking + trimmed exp path.
//   - R9 post-mortem: warp specialization fails (in-order warps -> exp warps
//     become the critical path). Mix must live INSIDE each warp's stream.
//   - R8 gap analysis: 80% co-saturation; tanh ops issued in bursts of 4
//     convoy the MUFU queue. Here each tanh pair's result is consumed
//     immediately and, in mixed steps, pair0's tanh ops are interleaved
//     into pair1's exp-FMA chain in program order.
//   - exp path computes s = L*(4-input) directly (folded coeffs, -2 instrs).

typedef unsigned long long u64;

__device__ __forceinline__ u64 pack2(float lo, float hi) {
    u64 r; asm("mov.b64 %0, {%1, %2};" : "=l"(r) : "f"(lo), "f"(hi)); return r;
}
__device__ __forceinline__ void unpack2(float& lo, float& hi, u64 v) {
    asm("mov.b64 {%0, %1}, %2;" : "=f"(lo), "=f"(hi) : "l"(v));
}
__device__ __forceinline__ u64 fma2(u64 a, u64 b, u64 c) {
    u64 d; asm("fma.rn.f32x2 %0, %1, %2, %3;" : "=l"(d) : "l"(a), "l"(b), "l"(c)); return d;
}
__device__ __forceinline__ u64 add2(u64 a, u64 b) {
    u64 d; asm("add.rn.f32x2 %0, %1, %2;" : "=l"(d) : "l"(a), "l"(b)); return d;
}
__device__ __forceinline__ u64 mul2(u64 a, u64 b) {
    u64 d; asm("mul.rn.f32x2 %0, %1, %2;" : "=l"(d) : "l"(a), "l"(b)); return d;
}
__device__ __forceinline__ float tanhf_a(float x) {
    float r; asm("tanh.approx.f32 %0, %1;" : "=f"(r) : "f"(x)); return r;
}

#define LOG2E 1.4426950408889634f
#define SIGN2 0x8000000080000000ULL

__global__ __launch_bounds__(128, 8)
void wilson_cowan_kernel(const float4* __restrict__ E0,
                         const float4* __restrict__ I0,
                         const float4* __restrict__ IextE,
                         const float4* __restrict__ IextI,
                         const int*    __restrict__ steps_ptr,
                         float* __restrict__ out,
                         int n, int n4, int out_size)
{
    int i = blockIdx.x * blockDim.x + threadIdx.x;

    if (blockIdx.x == 0 && threadIdx.x == 0) {
        for (int k = 2 * n; k < out_size; ++k) out[k] = 0.0f;
    }
    if (i >= n4) return;

    const int steps = steps_ptr ? __ldg(steps_ptr) : 100;

    float4 e4  = E0[i];
    float4 i4  = I0[i];
    float4 xe4 = IextE[i];
    float4 xi4 = IextI[i];

    u64 E2[2] = { pack2(e4.x, e4.y), pack2(e4.z, e4.w) };
    u64 I2[2] = { pack2(i4.x, i4.y), pack2(i4.z, i4.w) };
    // tanh-path per-pair constants: 0.5*(Iext-4)
    u64 cE2[2] = { pack2(0.5f*(xe4.x-4.0f), 0.5f*(xe4.y-4.0f)),
                   pack2(0.5f*(xe4.z-4.0f), 0.5f*(xe4.w-4.0f)) };
    u64 cI2[2] = { pack2(0.5f*(xi4.x-4.0f), 0.5f*(xi4.y-4.0f)),
                   pack2(0.5f*(xi4.z-4.0f), 0.5f*(xi4.w-4.0f)) };
    // exp-path constants for pair 1: L*(4-Iext)
    u64 sEc = pack2(LOG2E*(4.0f-xe4.z), LOG2E*(4.0f-xe4.w));
    u64 sIc = pack2(LOG2E*(4.0f-xi4.z), LOG2E*(4.0f-xi4.w));

    // tanh path: y = 0.5*(input-4); E' = 0.99E + 0.005(1+tanh(yE))
    const u64 AEE = pack2( 6.0f,  6.0f);
    const u64 AEI = pack2(-2.0f, -2.0f);
    const u64 AIE = pack2( 6.5f,  6.5f);
    const u64 AII = pack2(-5.5f, -5.5f);
    const u64 ME  = pack2(0.99f, 0.99f);
    const u64 MI  = pack2(0.98f, 0.98f);
    const u64 BE  = pack2(0.005f, 0.005f);
    const u64 BI  = pack2(0.01f,  0.01f);
    // exp path: s = L*(4-input); sigma = 1/(1+2^s); E' = 0.99E + 0.01*sigma
    const u64 XEE = pack2(-12.0f*LOG2E, -12.0f*LOG2E);
    const u64 XEI = pack2(  4.0f*LOG2E,   4.0f*LOG2E);
    const u64 XIE = pack2(-13.0f*LOG2E, -13.0f*LOG2E);
    const u64 XII = pack2( 11.0f*LOG2E,  11.0f*LOG2E);
    const u64 KI  = pack2(0.02f, 0.02f);
    const u64 MAG  = pack2(12582912.0f, 12582912.0f);   // 1.5*2^23
    const u64 NEG1 = pack2(-1.0f, -1.0f);
    const u64 ONE  = pack2( 1.0f,  1.0f);
    const u64 TWO  = pack2( 2.0f,  2.0f);
    const u64 A1 = pack2(0.69314718f, 0.69314718f);
    const u64 A2 = pack2(0.24022651f, 0.24022651f);
    const u64 A3 = pack2(0.05550411f, 0.05550411f);
    const u64 A4 = pack2(0.00961813f, 0.00961813f);

    // single tanh sub-step for one population of one pair: tanh results
    // consumed immediately (<=2 MUFU ops between FMA chunks)
    auto sig_upd = [&](u64& S, u64 y, u64 M, u64 B) {
        float a, b;
        unpack2(a, b, y);
        float ta = tanhf_a(a);
        float tb = tanhf_a(b);
        S = fma2(B, pack2(ta, tb), fma2(M, S, B));
    };

    auto tanh_step = [&](int p) {
        u64 yE = fma2(AEE, E2[p], fma2(AEI, I2[p], cE2[p]));
        u64 yI = fma2(AIE, E2[p], fma2(AII, I2[p], cI2[p]));
        u64 Eold = E2[p];
        sig_upd(E2[p], yE, ME, BE);      // yI's fma already in flight
        (void)Eold;
        sig_upd(I2[p], yI, MI, BI);
    };

    // one 2^s polynomial piece (no splice): 7 fma-pipe ops
    auto exp2_poly = [&](u64 s2, u64& m2out) -> u64 {
        u64 m2 = add2(s2, MAG);            // low bits hold rint(s)
        u64 d2 = fma2(MAG, NEG1, m2);      // float(rint(s)), exact
        u64 f2 = fma2(d2, NEG1, s2);       // f in [-0.5, 0.5]
        u64 p  = fma2(A4, f2, A3);
        p = fma2(p, f2, A2);
        p = fma2(p, f2, A1);
        p = fma2(p, f2, ONE);
        m2out = m2;
        return p;
    };
    auto splice = [&](u64 p, u64 m2) -> u64 {   // z = p * 2^rint(s), ALU ops
        float mlo, mhi, plo, phi;
        unpack2(mlo, mhi, m2);
        unpack2(plo, phi, p);
        int zlo = __float_as_int(plo) + (__float_as_int(mlo) << 23);
        int zhi = __float_as_int(phi) + (__float_as_int(mhi) << 23);
        return pack2(__int_as_float(zlo), __int_as_float(zhi));
    };

    // mixed step: pair0 tanh interleaved INTO pair1's exp-FMA chain
    auto mixed_step = [&]() {
        // pair1 exp: compute s directly
        u64 sE = fma2(XEE, E2[1], fma2(XEI, I2[1], sEc));   // [-11.6, 11.6]
        u64 sI = fma2(XIE, E2[1], fma2(XII, I2[1], sIc));   // [-13.0, 21.7]
        // pair0 y
        u64 yE0 = fma2(AEE, E2[0], fma2(AEI, I2[0], cE2[0]));
        u64 yI0 = fma2(AIE, E2[0], fma2(AII, I2[0], cI2[0]));
        // tanh burst #1 (2 ops) amid exp poly E
        float a, b;
        unpack2(a, b, yE0);
        float tEa = tanhf_a(a);
        u64 mE, mI;
        u64 pE = exp2_poly(sE, mE);        // 7 FMA ops overlap tanh latency
        float tEb = tanhf_a(b);
        E2[0] = fma2(BE, pack2(tEa, tEb), fma2(ME, E2[0], BE));
        // tanh burst #2 amid exp poly I
        unpack2(a, b, yI0);
        float tIa = tanhf_a(a);
        u64 pI = exp2_poly(sI, mI);
        float tIb = tanhf_a(b);
        I2[0] = fma2(BI, pack2(tIa, tIb), fma2(MI, I2[0], BI));
        // finish pair1 exp
        u64 zE = splice(pE, mE);
        u64 zI = splice(pI, mI);
        u64 wE = add2(zE, ONE);
        u64 wI = add2(zI, ONE);
        u64 P  = mul2(wE, wI);             // <= ~1e10, normal
        float plo, phi;
        unpack2(plo, phi, P);
        u64 r = pack2(__int_as_float(0x7EF311C3 - __float_as_int(plo)),
                      __int_as_float(0x7EF311C3 - __float_as_int(phi)));
        r = mul2(r, fma2(P, r ^ SIGN2, TWO));   // Newton 1
        r = mul2(r, fma2(P, r ^ SIGN2, TWO));   // Newton 2: rel err ~1e-6
        u64 gE = mul2(r, wI);              // sigma_E = 1/wE
        u64 gI = mul2(r, wE);              // sigma_I = 1/wI
        E2[1] = fma2(BI, gE, mul2(ME, E2[1]));  // kE = 0.01 == BI
        I2[1] = fma2(KI, gI, mul2(MI, I2[1]));
    };

    // 5-step dither blocks: pair1 exp on steps 2 and 4 (global x = 0.2)
    int b5  = steps / 5;
    int rem = steps - b5 * 5;
    for (int b = 0; b < b5; ++b) {
        tanh_step(0); tanh_step(1);
        tanh_step(0); tanh_step(1);
        mixed_step();
        tanh_step(0); tanh_step(1);
        mixed_step();
    }
    for (int s = 0; s < rem; ++s) {
        tanh_step(0); tanh_step(1);
    }

    float4 eo, io;
    unpack2(eo.x, eo.y, E2[0]); unpack2(eo.z, eo.w, E2[1]);
    unpack2(io.x, io.y, I2[0]); unpack2(io.z, io.w, I2[1]);
    eo.x = __saturatef(eo.x); eo.y = __saturatef(eo.y);
    eo.z = __saturatef(eo.z); eo.w = __saturatef(eo.w);
    io.x = __saturatef(io.x); io.y = __saturatef(io.y);
    io.z = __saturatef(io.z); io.w = __saturatef(io.w);

    reinterpret_cast<float4*>(out)[i]     = eo;
    reinterpret_cast<float4*>(out + n)[i] = io;
}

extern "C" void kernel_launch(void* const* d_in, const int* in_sizes, int n_in,
                              void* d_out, int out_size)
{
    const float4* E0    = (const float4*)d_in[0];
    const float4* I0    = (const float4*)d_in[1];
    const float4* IextE = (const float4*)d_in[2];
    const float4* IextI = (const float4*)d_in[3];
    const int* steps_ptr = (n_in >= 5) ? (const int*)d_in[4] : nullptr;

    int n = in_sizes[0];
    int n4 = n / 4;                     // 4 elems per thread = 1 float4
    int threads = 128;
    int blocks = (n4 + threads - 1) / threads;   // 2048

    wilson_cowan_kernel<<<blocks, threads>>>(E0, I0, IextE, IextI, steps_ptr,
                                             (float*)d_out, n, n4, out_size);
}